// round 8
// baseline (speedup 1.0000x reference)
#include <cuda_runtime.h>
#include <cstdint>

// Problem constants (fixed shapes from the reference)
#define NPIX    (8 * 512 * 512)     // N*H*W = 2,097,152
#define HW_SH   18                  // log2(512*512)
#define FCOUNT  100000
#define SIGMA_INV   10000.0f        // 1/SIGMA
#define GAMMA_INV   10000.0f        // 1/GAMMA
#define ZFARC       100.0f
#define INV_ZRANGE  (1.0f / 99.0f)  // 1/(ZFAR-ZNEAR)
#define EPSB        1e-10f

#define TPB     128
#define NWARP   (TPB / 32)

// Packed per-face records: 128B-aligned, 5 float4s used (18 floats):
//  [v0.xyz v1.x | v1.yz v2.xy | v2.z n0.xyz | n1.xyz n2.x | n2.yz - -]
__device__ float4 g_face_table[(size_t)FCOUNT * 8];   // 12.8 MB static scratch

// compile-time-immediate cp.async.wait_group (fixes the R5 compile error)
template <int N>
__device__ __forceinline__ void cp_async_wait()
{
    asm volatile("cp.async.wait_group %0;\n" :: "n"(N));
}

// ---------------------------------------------------------------------------
// Kernel 1: gather verts/normals per face into line-aligned records.
// ---------------------------------------------------------------------------
__global__ void __launch_bounds__(256)
pack_faces(const int* __restrict__ faces,
           const float* __restrict__ verts,
           const float* __restrict__ vnorm)
{
    int f = blockIdx.x * blockDim.x + threadIdx.x;
    if (f >= FCOUNT) return;
    int i0 = __ldg(faces + 3 * f + 0);
    int i1 = __ldg(faces + 3 * f + 1);
    int i2 = __ldg(faces + 3 * f + 2);

    float v0x = __ldg(verts + 3 * i0 + 0), v0y = __ldg(verts + 3 * i0 + 1), v0z = __ldg(verts + 3 * i0 + 2);
    float v1x = __ldg(verts + 3 * i1 + 0), v1y = __ldg(verts + 3 * i1 + 1), v1z = __ldg(verts + 3 * i1 + 2);
    float v2x = __ldg(verts + 3 * i2 + 0), v2y = __ldg(verts + 3 * i2 + 1), v2z = __ldg(verts + 3 * i2 + 2);
    float n0x = __ldg(vnorm + 3 * i0 + 0), n0y = __ldg(vnorm + 3 * i0 + 1), n0z = __ldg(vnorm + 3 * i0 + 2);
    float n1x = __ldg(vnorm + 3 * i1 + 0), n1y = __ldg(vnorm + 3 * i1 + 1), n1z = __ldg(vnorm + 3 * i1 + 2);
    float n2x = __ldg(vnorm + 3 * i2 + 0), n2y = __ldg(vnorm + 3 * i2 + 1), n2z = __ldg(vnorm + 3 * i2 + 2);

    float4* rec = g_face_table + (size_t)f * 8;
    rec[0] = make_float4(v0x, v0y, v0z, v1x);
    rec[1] = make_float4(v1y, v1z, v2x, v2y);
    rec[2] = make_float4(v2z, n0x, n0y, n0z);
    rec[3] = make_float4(n1x, n1y, n1z, n2x);
    rec[4] = make_float4(n2y, n2z, 0.0f, 0.0f);
}

// reference normalize: x / max(||x||, 1e-6)  ==  x * min(rsqrt(||x||^2), 1e6)
__device__ __forceinline__ float safe_rnorm(float n2)
{
    return fminf(rsqrtf(n2), 1e6f);
}

// ---------------------------------------------------------------------------
// Kernel 2: shade + softmax blend.
//  - depth-4 cp.async.cg pipeline: all 4 fragments' face records prefetched
//    into SMEM (L1-bypassed) before the compute loop
//  - blend weights computed BEFORE the gather loop; colors accumulated in-loop
// ---------------------------------------------------------------------------
__global__ void __launch_bounds__(TPB, 5)
shade(const float4* __restrict__ bary,     // NPIX*3 float4 (12 floats/pixel)
      const float4* __restrict__ zb,       // NPIX
      const float4* __restrict__ ds,       // NPIX
      const float4* __restrict__ tx,       // NPIX*3
      const float*  __restrict__ vis,      // NPIX*3
      const int4*   __restrict__ p2f,      // NPIX
      const float*  __restrict__ l_loc,
      const float*  __restrict__ l_amb,
      const float*  __restrict__ l_dif,
      const float*  __restrict__ l_spc,
      const float*  __restrict__ cam,
      const float*  __restrict__ m_amb,
      const float*  __restrict__ m_dif,
      const float*  __restrict__ m_spc,
      const float*  __restrict__ shin,
      float4*       __restrict__ out)
{
    __shared__ float4 s_rec[4 * NWARP * 160];   // [stage][warp][160] = 40 KB
    const int P    = blockIdx.x * TPB + threadIdx.x;   // grid covers NPIX exactly
    const int lane = threadIdx.x & 31;
    const int wid  = threadIdx.x >> 5;

    // ---- face ids first: they gate the prefetch ----
    const int4 f4 = __ldg(p2f + P);
    const int  fk[4] = { f4.x, f4.y, f4.z, f4.w };

    // ---- fire all 4 stages of the gather pipeline (20 x 16B cp.async/lane) ----
#pragma unroll
    for (int k = 0; k < 4; k++) {
        float4* sw = s_rec + (k * NWARP + wid) * 160;
        const int fc = max(fk[k], 0);
#pragma unroll
        for (int j = 0; j < 5; j++) {
            int t = j * 32 + lane;
            int r = t / 5;
            int p = t - 5 * r;
            int fr = __shfl_sync(0xffffffffu, fc, r);
            const float4* src = g_face_table + (size_t)fr * 8 + p;
            uint32_t dst = (uint32_t)__cvta_generic_to_shared(sw + t);
            asm volatile("cp.async.cg.shared.global [%0], [%1], 16;\n"
                         :: "r"(dst), "l"(src));
        }
        asm volatile("cp.async.commit_group;\n");
    }

    // ---- per-image params (warp-uniform broadcast loads) ----
    const int n = P >> HW_SH;
    const float llx = __ldg(l_loc + 3 * n), lly = __ldg(l_loc + 3 * n + 1), llz = __ldg(l_loc + 3 * n + 2);
    const float ccx = __ldg(cam   + 3 * n), ccy = __ldg(cam   + 3 * n + 1), ccz = __ldg(cam   + 3 * n + 2);
    const float ambr = __ldg(m_amb + 3 * n + 0) * __ldg(l_amb + 3 * n + 0);
    const float ambg = __ldg(m_amb + 3 * n + 1) * __ldg(l_amb + 3 * n + 1);
    const float ambb = __ldg(m_amb + 3 * n + 2) * __ldg(l_amb + 3 * n + 2);
    const float kdr  = __ldg(m_dif + 3 * n + 0) * __ldg(l_dif + 3 * n + 0);
    const float kdg  = __ldg(m_dif + 3 * n + 1) * __ldg(l_dif + 3 * n + 1);
    const float kdb  = __ldg(m_dif + 3 * n + 2) * __ldg(l_dif + 3 * n + 2);
    const float ksr  = __ldg(m_spc + 3 * n + 0) * __ldg(l_spc + 3 * n + 0);
    const float ksg  = __ldg(m_spc + 3 * n + 1) * __ldg(l_spc + 3 * n + 1);
    const float ksb  = __ldg(m_spc + 3 * n + 2) * __ldg(l_spc + 3 * n + 2);
    const float sh   = __ldg(shin + n);

    // ---- blend weights (need only zbuf/dists/mask; done before gather lands) ----
    const float4 z4 = __ldg(zb + P);
    const float4 d4 = __ldg(ds + P);
    const float zkk[4] = { z4.x, z4.y, z4.z, z4.w };
    const float dkk[4] = { d4.x, d4.y, d4.z, d4.w };

    float prob[4], zi[4];
#pragma unroll
    for (int k = 0; k < 4; k++) {
        const bool m = (fk[k] >= 0);
        prob[k] = m ? __fdividef(1.0f, 1.0f + __expf(dkk[k] * SIGMA_INV)) : 0.0f;
        zi[k]   = m ? (ZFARC - zkk[k]) * INV_ZRANGE : 0.0f;
    }
    const float zmax  = fmaxf(fmaxf(fmaxf(zi[0], zi[1]), fmaxf(zi[2], zi[3])), EPSB);
    const float alpha = 1.0f - (1.0f - prob[0]) * (1.0f - prob[1]) * (1.0f - prob[2]) * (1.0f - prob[3]);

    float wk[4], wsum = 0.0f;
#pragma unroll
    for (int k = 0; k < 4; k++) {
        wk[k] = prob[k] * __expf((zi[k] - zmax) * GAMMA_INV);
        wsum += wk[k];
    }
    const float delta = __expf((EPSB - zmax) * GAMMA_INV);
    const float inv   = 1.0f / (wsum + delta);      // BG=(1,1,1) -> delta*BG = delta

    // ---- remaining per-pixel streams ----
    const float4 q0 = __ldg(bary + 3 * P + 0);
    const float4 q1 = __ldg(bary + 3 * P + 1);
    const float4 q2 = __ldg(bary + 3 * P + 2);
    const float4 t0 = __ldg(tx + 3 * P + 0);
    const float4 t1 = __ldg(tx + 3 * P + 1);
    const float4 t2 = __ldg(tx + 3 * P + 2);
    const float  vr = __ldg(vis + 3 * P + 0);
    const float  vg = __ldg(vis + 3 * P + 1);
    const float  vb = __ldg(vis + 3 * P + 2);

    const float bxk[4] = { q0.x, q0.w, q1.z, q2.y };
    const float byk[4] = { q0.y, q1.x, q1.w, q2.z };
    const float bzk[4] = { q0.z, q1.y, q2.x, q2.w };
    const float txr[4] = { t0.x, t0.w, t1.z, t2.y };
    const float txg[4] = { t0.y, t1.x, t1.w, t2.z };
    const float txb[4] = { t0.z, t1.y, t2.x, t2.w };

    float sr = 0.0f, sg = 0.0f, sb = 0.0f;

#pragma unroll
    for (int k = 0; k < 4; k++) {
        // drain stage k of the pipeline (compile-time immediates via template;
        // after the warp-wide wait + syncwarp, stage-k data is SMEM-resident)
        switch (k) {
            case 0: cp_async_wait<3>(); break;
            case 1: cp_async_wait<2>(); break;
            case 2: cp_async_wait<1>(); break;
            default: cp_async_wait<0>(); break;
        }
        __syncwarp();

        const float4* s = s_rec + (k * NWARP + wid) * 160;
        const float4 a0 = s[lane * 5 + 0];   // stride-5 float4: conflict-free LDS.128
        const float4 a1 = s[lane * 5 + 1];
        const float4 a2 = s[lane * 5 + 2];
        const float4 a3 = s[lane * 5 + 3];
        const float4 a4 = s[lane * 5 + 4];

        // ---- barycentric interpolation ----
        const float b0 = bxk[k], b1 = byk[k], b2 = bzk[k];
        const float pcx = b0 * a0.x + b1 * a0.w + b2 * a1.z;
        const float pcy = b0 * a0.y + b1 * a1.x + b2 * a1.w;
        const float pcz = b0 * a0.z + b1 * a1.y + b2 * a2.x;
        const float pnx = b0 * a2.y + b1 * a3.x + b2 * a3.w;
        const float pny = b0 * a2.z + b1 * a3.y + b2 * a4.x;
        const float pnz = b0 * a2.w + b1 * a3.z + b2 * a4.y;

        // ---- Phong shading ----
        const float rn = safe_rnorm(pnx * pnx + pny * pny + pnz * pnz);
        const float nx = pnx * rn, ny = pny * rn, nz = pnz * rn;

        float dx = llx - pcx, dy = lly - pcy, dz = llz - pcz;
        const float rd = safe_rnorm(dx * dx + dy * dy + dz * dz);
        dx *= rd; dy *= rd; dz *= rd;

        const float cosA = nx * dx + ny * dy + nz * dz;
        const float rc   = fmaxf(cosA, 0.0f);

        const float rfx = 2.0f * cosA * nx - dx;
        const float rfy = 2.0f * cosA * ny - dy;
        const float rfz = 2.0f * cosA * nz - dz;

        const float vx = ccx - pcx, vy = ccy - pcy, vz = ccz - pcz;
        const float rv = safe_rnorm(vx * vx + vy * vy + vz * vz);
        float sc = (vx * rfx + vy * rfy + vz * rfz) * rv;
        sc = fmaxf(sc, 0.0f);
        const float spec = (cosA > 0.0f && sc > 0.0f) ? __powf(sc, sh) : 0.0f;

        // ---- weighted color accumulation (weight already known) ----
        const float w = wk[k];
        sr += w * ((ambr + kdr * rc * vr) * txr[k] + ksr * spec);
        sg += w * ((ambg + kdg * rc * vg) * txg[k] + ksg * spec);
        sb += w * ((ambb + kdb * rc * vb) * txb[k] + ksb * spec);
    }

    out[P] = make_float4((sr + delta) * inv, (sg + delta) * inv, (sb + delta) * inv, alpha);
}

// ---------------------------------------------------------------------------
// Input order (metadata.txt / setup_inputs order):
//  0 verts  1 vertex_normals  2 bary_coords  3 zbuf  4 dists  5 texels
//  6 vis_maps  7 light_location  8 light_ambient  9 light_diffuse
// 10 light_specular 11 camera_center 12 mat_ambient 13 mat_diffuse
// 14 mat_specular 15 shininess 16 faces 17 pix_to_face
// ---------------------------------------------------------------------------
extern "C" void kernel_launch(void* const* d_in, const int* in_sizes, int n_in,
                              void* d_out, int out_size)
{
    (void)in_sizes; (void)n_in; (void)out_size;

    const float* verts  = (const float*)d_in[0];
    const float* vnorm  = (const float*)d_in[1];
    const float4* bary  = (const float4*)d_in[2];
    const float4* zb    = (const float4*)d_in[3];
    const float4* ds    = (const float4*)d_in[4];
    const float4* tx    = (const float4*)d_in[5];
    const float*  vis   = (const float*)d_in[6];
    const float*  l_loc = (const float*)d_in[7];
    const float*  l_amb = (const float*)d_in[8];
    const float*  l_dif = (const float*)d_in[9];
    const float*  l_spc = (const float*)d_in[10];
    const float*  cam   = (const float*)d_in[11];
    const float*  m_amb = (const float*)d_in[12];
    const float*  m_dif = (const float*)d_in[13];
    const float*  m_spc = (const float*)d_in[14];
    const float*  shin  = (const float*)d_in[15];
    const int*    faces = (const int*)d_in[16];
    const int4*   p2f   = (const int4*)d_in[17];
    float4* out = (float4*)d_out;

    pack_faces<<<(FCOUNT + 255) / 256, 256>>>(faces, verts, vnorm);
    shade<<<NPIX / TPB, TPB>>>(bary, zb, ds, tx, vis, p2f,
                               l_loc, l_amb, l_dif, l_spc, cam,
                               m_amb, m_dif, m_spc, shin, out);
}

// round 13
// speedup vs baseline: 3.9806x; 3.9806x over previous
#include <cuda_runtime.h>
#include <cstdint>

// Problem constants (fixed shapes from the reference)
#define NPIX    (8 * 512 * 512)     // N*H*W = 2,097,152 (divisible by 256)
#define HW_SH   18                  // log2(512*512)
#define FCOUNT  100000
#define SIGMA_INV   10000.0f        // 1/SIGMA
#define GAMMA_INV   10000.0f        // 1/GAMMA
#define ZFARC       100.0f
#define INV_ZRANGE  (1.0f / 99.0f)  // 1/(ZFAR-ZNEAR)
#define EPSB        1e-10f

// Packed per-face records: 128B-aligned, 5 float4s used (18 floats):
//  [v0.xyz v1.x | v1.yz v2.xy | v2.z n0.xyz | n1.xyz n2.x | n2.yz - -]
__device__ float4 g_face_table[(size_t)FCOUNT * 8];   // 12.8 MB static scratch

// ---------------------------------------------------------------------------
// Kernel 1: gather verts/normals per face into line-aligned records.
// ---------------------------------------------------------------------------
__global__ void __launch_bounds__(256)
pack_faces(const int* __restrict__ faces,
           const float* __restrict__ verts,
           const float* __restrict__ vnorm)
{
    int f = blockIdx.x * blockDim.x + threadIdx.x;
    if (f >= FCOUNT) return;
    int i0 = __ldg(faces + 3 * f + 0);
    int i1 = __ldg(faces + 3 * f + 1);
    int i2 = __ldg(faces + 3 * f + 2);

    float v0x = __ldg(verts + 3 * i0 + 0), v0y = __ldg(verts + 3 * i0 + 1), v0z = __ldg(verts + 3 * i0 + 2);
    float v1x = __ldg(verts + 3 * i1 + 0), v1y = __ldg(verts + 3 * i1 + 1), v1z = __ldg(verts + 3 * i1 + 2);
    float v2x = __ldg(verts + 3 * i2 + 0), v2y = __ldg(verts + 3 * i2 + 1), v2z = __ldg(verts + 3 * i2 + 2);
    float n0x = __ldg(vnorm + 3 * i0 + 0), n0y = __ldg(vnorm + 3 * i0 + 1), n0z = __ldg(vnorm + 3 * i0 + 2);
    float n1x = __ldg(vnorm + 3 * i1 + 0), n1y = __ldg(vnorm + 3 * i1 + 1), n1z = __ldg(vnorm + 3 * i1 + 2);
    float n2x = __ldg(vnorm + 3 * i2 + 0), n2y = __ldg(vnorm + 3 * i2 + 1), n2z = __ldg(vnorm + 3 * i2 + 2);

    float4* rec = g_face_table + (size_t)f * 8;
    rec[0] = make_float4(v0x, v0y, v0z, v1x);
    rec[1] = make_float4(v1y, v1z, v2x, v2y);
    rec[2] = make_float4(v2z, n0x, n0y, n0z);
    rec[3] = make_float4(n1x, n1y, n1z, n2x);
    rec[4] = make_float4(n2y, n2z, 0.0f, 0.0f);
}

// reference normalize: x / max(||x||, 1e-6)  ==  x * min(rsqrt(||x||^2), 1e6)
__device__ __forceinline__ float safe_rnorm(float n2)
{
    return fminf(rsqrtf(n2), 1e6f);
}

// Cooperative record gather for one fragment stage: 5 coalesced LDG.128 per
// warp (L2-only via __ldcg; the 12.8MB table has zero L1 reuse).
__device__ __forceinline__ void gather_stage(int fc, int lane, float4 (&R)[5])
{
#pragma unroll
    for (int j = 0; j < 5; j++) {
        const int t = j * 32 + lane;
        const int r = t / 5;
        const int p = t - 5 * r;
        const int fr = __shfl_sync(0xffffffffu, fc, r);
        R[j] = __ldcg(reinterpret_cast<const float4*>(g_face_table) + (size_t)fr * 8 + p);
    }
}

// ---------------------------------------------------------------------------
// Kernel 2: shade + softmax blend. Proven LDG+STS+LDS cooperative gather
// (R4 structure) + one-stage-ahead register prefetch + L1-bypass streams +
// weights-before-gather restructure.
// ---------------------------------------------------------------------------
__global__ void __launch_bounds__(256)
shade(const float4* __restrict__ bary,     // NPIX*3 float4 (12 floats/pixel)
      const float4* __restrict__ zb,       // NPIX
      const float4* __restrict__ ds,       // NPIX
      const float4* __restrict__ tx,       // NPIX*3
      const float*  __restrict__ vis,      // NPIX*3
      const int4*   __restrict__ p2f,      // NPIX
      const float*  __restrict__ l_loc,
      const float*  __restrict__ l_amb,
      const float*  __restrict__ l_dif,
      const float*  __restrict__ l_spc,
      const float*  __restrict__ cam,
      const float*  __restrict__ m_amb,
      const float*  __restrict__ m_dif,
      const float*  __restrict__ m_spc,
      const float*  __restrict__ shin,
      float4*       __restrict__ out)
{
    __shared__ float4 s_rec[8 * 160];      // 8 warps * 32 records * 5 float4 = 20KB
    const int P    = blockIdx.x * 256 + threadIdx.x;   // grid covers NPIX exactly
    const int lane = threadIdx.x & 31;
    float4* s = s_rec + (threadIdx.x >> 5) * 160;
    const int n = P >> HW_SH;

    // ---- face ids first: they gate the gather pipeline ----
    const int4 f4 = __ldg(p2f + P);
    const int  fk[4] = { f4.x, f4.y, f4.z, f4.w };

    // ---- prologue: stage-0 records in flight while we do everything else ----
    float4 R[5];
    gather_stage(max(fk[0], 0), lane, R);

    // ---- per-image params (warp-uniform broadcast loads, L1-cached) ----
    const float llx = __ldg(l_loc + 3 * n), lly = __ldg(l_loc + 3 * n + 1), llz = __ldg(l_loc + 3 * n + 2);
    const float ccx = __ldg(cam   + 3 * n), ccy = __ldg(cam   + 3 * n + 1), ccz = __ldg(cam   + 3 * n + 2);
    const float ambr = __ldg(m_amb + 3 * n + 0) * __ldg(l_amb + 3 * n + 0);
    const float ambg = __ldg(m_amb + 3 * n + 1) * __ldg(l_amb + 3 * n + 1);
    const float ambb = __ldg(m_amb + 3 * n + 2) * __ldg(l_amb + 3 * n + 2);
    const float kdr  = __ldg(m_dif + 3 * n + 0) * __ldg(l_dif + 3 * n + 0);
    const float kdg  = __ldg(m_dif + 3 * n + 1) * __ldg(l_dif + 3 * n + 1);
    const float kdb  = __ldg(m_dif + 3 * n + 2) * __ldg(l_dif + 3 * n + 2);
    const float ksr  = __ldg(m_spc + 3 * n + 0) * __ldg(l_spc + 3 * n + 0);
    const float ksg  = __ldg(m_spc + 3 * n + 1) * __ldg(l_spc + 3 * n + 1);
    const float ksb  = __ldg(m_spc + 3 * n + 2) * __ldg(l_spc + 3 * n + 2);
    const float sh   = __ldg(shin + n);

    // ---- blend weights (independent of the gather; overlaps its latency) ----
    const float4 z4 = __ldcg(zb + P);
    const float4 d4 = __ldcg(ds + P);
    const float zkk[4] = { z4.x, z4.y, z4.z, z4.w };
    const float dkk[4] = { d4.x, d4.y, d4.z, d4.w };

    float prob[4], zi[4];
#pragma unroll
    for (int k = 0; k < 4; k++) {
        const bool m = (fk[k] >= 0);
        prob[k] = m ? __fdividef(1.0f, 1.0f + __expf(dkk[k] * SIGMA_INV)) : 0.0f;
        zi[k]   = m ? (ZFARC - zkk[k]) * INV_ZRANGE : 0.0f;
    }
    const float zmax  = fmaxf(fmaxf(fmaxf(zi[0], zi[1]), fmaxf(zi[2], zi[3])), EPSB);
    const float alpha = 1.0f - (1.0f - prob[0]) * (1.0f - prob[1]) * (1.0f - prob[2]) * (1.0f - prob[3]);

    float wk[4], wsum = 0.0f;
#pragma unroll
    for (int k = 0; k < 4; k++) {
        wk[k] = prob[k] * __expf((zi[k] - zmax) * GAMMA_INV);
        wsum += wk[k];
    }
    const float delta = __expf((EPSB - zmax) * GAMMA_INV);
    const float inv   = 1.0f / (wsum + delta);      // BG=(1,1,1) -> delta*BG = delta

    // ---- remaining per-pixel streams (zero reuse -> L2-only) ----
    const float4 q0 = __ldcg(bary + 3 * P + 0);
    const float4 q1 = __ldcg(bary + 3 * P + 1);
    const float4 q2 = __ldcg(bary + 3 * P + 2);
    const float4 t0 = __ldcg(tx + 3 * P + 0);
    const float4 t1 = __ldcg(tx + 3 * P + 1);
    const float4 t2 = __ldcg(tx + 3 * P + 2);
    const float  vr = __ldcg(vis + 3 * P + 0);
    const float  vg = __ldcg(vis + 3 * P + 1);
    const float  vb = __ldcg(vis + 3 * P + 2);

    const float bxk[4] = { q0.x, q0.w, q1.z, q2.y };
    const float byk[4] = { q0.y, q1.x, q1.w, q2.z };
    const float bzk[4] = { q0.z, q1.y, q2.x, q2.w };
    const float txr[4] = { t0.x, t0.w, t1.z, t2.y };
    const float txg[4] = { t0.y, t1.x, t1.w, t2.z };
    const float txb[4] = { t0.z, t1.y, t2.x, t2.w };

    float sr = 0.0f, sg = 0.0f, sb = 0.0f;

#pragma unroll
    for (int k = 0; k < 4; k++) {
        // park stage k in SMEM (waits on its LDGs via scoreboard)
#pragma unroll
        for (int j = 0; j < 5; j++)
            s[j * 32 + lane] = R[j];

        // fire stage k+1 LDGs immediately: latency hides behind compute k
        float4 T[5];
        if (k < 3)
            gather_stage(max(fk[k + 1], 0), lane, T);

        __syncwarp();
        const float4 a0 = s[lane * 5 + 0];   // stride-5 float4: conflict-free LDS.128
        const float4 a1 = s[lane * 5 + 1];
        const float4 a2 = s[lane * 5 + 2];
        const float4 a3 = s[lane * 5 + 3];
        const float4 a4 = s[lane * 5 + 4];
        __syncwarp();                        // reads done before next iter's STS

        // ---- barycentric interpolation ----
        const float b0 = bxk[k], b1 = byk[k], b2 = bzk[k];
        const float pcx = b0 * a0.x + b1 * a0.w + b2 * a1.z;
        const float pcy = b0 * a0.y + b1 * a1.x + b2 * a1.w;
        const float pcz = b0 * a0.z + b1 * a1.y + b2 * a2.x;
        const float pnx = b0 * a2.y + b1 * a3.x + b2 * a3.w;
        const float pny = b0 * a2.z + b1 * a3.y + b2 * a4.x;
        const float pnz = b0 * a2.w + b1 * a3.z + b2 * a4.y;

        // ---- Phong shading ----
        const float rn = safe_rnorm(pnx * pnx + pny * pny + pnz * pnz);
        const float nx = pnx * rn, ny = pny * rn, nz = pnz * rn;

        float dx = llx - pcx, dy = lly - pcy, dz = llz - pcz;
        const float rd = safe_rnorm(dx * dx + dy * dy + dz * dz);
        dx *= rd; dy *= rd; dz *= rd;

        const float cosA = nx * dx + ny * dy + nz * dz;
        const float rc   = fmaxf(cosA, 0.0f);

        const float rfx = 2.0f * cosA * nx - dx;
        const float rfy = 2.0f * cosA * ny - dy;
        const float rfz = 2.0f * cosA * nz - dz;

        const float vx = ccx - pcx, vy = ccy - pcy, vz = ccz - pcz;
        const float rv = safe_rnorm(vx * vx + vy * vy + vz * vz);
        float sc = (vx * rfx + vy * rfy + vz * rfz) * rv;
        sc = fmaxf(sc, 0.0f);
        const float spec = (cosA > 0.0f && sc > 0.0f) ? __powf(sc, sh) : 0.0f;

        // ---- weighted color accumulation (weight already known) ----
        const float w = wk[k];
        sr += w * ((ambr + kdr * rc * vr) * txr[k] + ksr * spec);
        sg += w * ((ambg + kdg * rc * vg) * txg[k] + ksg * spec);
        sb += w * ((ambb + kdb * rc * vb) * txb[k] + ksb * spec);

        // rotate the pipeline registers (full unroll -> pure renaming)
        if (k < 3) {
#pragma unroll
            for (int j = 0; j < 5; j++)
                R[j] = T[j];
        }
    }

    out[P] = make_float4((sr + delta) * inv, (sg + delta) * inv, (sb + delta) * inv, alpha);
}

// ---------------------------------------------------------------------------
// Input order (metadata.txt / setup_inputs order):
//  0 verts  1 vertex_normals  2 bary_coords  3 zbuf  4 dists  5 texels
//  6 vis_maps  7 light_location  8 light_ambient  9 light_diffuse
// 10 light_specular 11 camera_center 12 mat_ambient 13 mat_diffuse
// 14 mat_specular 15 shininess 16 faces 17 pix_to_face
// ---------------------------------------------------------------------------
extern "C" void kernel_launch(void* const* d_in, const int* in_sizes, int n_in,
                              void* d_out, int out_size)
{
    (void)in_sizes; (void)n_in; (void)out_size;

    const float* verts  = (const float*)d_in[0];
    const float* vnorm  = (const float*)d_in[1];
    const float4* bary  = (const float4*)d_in[2];
    const float4* zb    = (const float4*)d_in[3];
    const float4* ds    = (const float4*)d_in[4];
    const float4* tx    = (const float4*)d_in[5];
    const float*  vis   = (const float*)d_in[6];
    const float*  l_loc = (const float*)d_in[7];
    const float*  l_amb = (const float*)d_in[8];
    const float*  l_dif = (const float*)d_in[9];
    const float*  l_spc = (const float*)d_in[10];
    const float*  cam   = (const float*)d_in[11];
    const float*  m_amb = (const float*)d_in[12];
    const float*  m_dif = (const float*)d_in[13];
    const float*  m_spc = (const float*)d_in[14];
    const float*  shin  = (const float*)d_in[15];
    const int*    faces = (const int*)d_in[16];
    const int4*   p2f   = (const int4*)d_in[17];
    float4* out = (float4*)d_out;

    pack_faces<<<(FCOUNT + 255) / 256, 256>>>(faces, verts, vnorm);
    shade<<<NPIX / 256, 256>>>(bary, zb, ds, tx, vis, p2f,
                               l_loc, l_amb, l_dif, l_spc, cam,
                               m_amb, m_dif, m_spc, shin, out);
}

// round 14
// speedup vs baseline: 7.6877x; 1.9313x over previous
#include <cuda_runtime.h>
#include <cstdint>

// Problem constants (fixed shapes from the reference)
#define NPIX    (8 * 512 * 512)     // N*H*W = 2,097,152
#define NFRAG   (NPIX * 4)          // 8,388,608 fragments (K=4)
#define FCOUNT  100000
#define SIGMA_INV   10000.0f        // 1/SIGMA
#define GAMMA_INV   10000.0f        // 1/GAMMA
#define ZFARC       100.0f
#define INV_ZRANGE  (1.0f / 99.0f)  // 1/(ZFAR-ZNEAR)
#define EPSB        1e-10f

// Packed per-face records: 128B-aligned, 5 float4s used (18 floats):
//  [v0.xyz v1.x | v1.yz v2.xy | v2.z n0.xyz | n1.xyz n2.x | n2.yz - -]
__device__ float4 g_face_table[(size_t)FCOUNT * 8];   // 12.8 MB static scratch

// ---------------------------------------------------------------------------
// Kernel 1: gather verts/normals per face into line-aligned records.
// ---------------------------------------------------------------------------
__global__ void __launch_bounds__(256)
pack_faces(const int* __restrict__ faces,
           const float* __restrict__ verts,
           const float* __restrict__ vnorm)
{
    int f = blockIdx.x * blockDim.x + threadIdx.x;
    if (f >= FCOUNT) return;
    int i0 = __ldg(faces + 3 * f + 0);
    int i1 = __ldg(faces + 3 * f + 1);
    int i2 = __ldg(faces + 3 * f + 2);

    float v0x = __ldg(verts + 3 * i0 + 0), v0y = __ldg(verts + 3 * i0 + 1), v0z = __ldg(verts + 3 * i0 + 2);
    float v1x = __ldg(verts + 3 * i1 + 0), v1y = __ldg(verts + 3 * i1 + 1), v1z = __ldg(verts + 3 * i1 + 2);
    float v2x = __ldg(verts + 3 * i2 + 0), v2y = __ldg(verts + 3 * i2 + 1), v2z = __ldg(verts + 3 * i2 + 2);
    float n0x = __ldg(vnorm + 3 * i0 + 0), n0y = __ldg(vnorm + 3 * i0 + 1), n0z = __ldg(vnorm + 3 * i0 + 2);
    float n1x = __ldg(vnorm + 3 * i1 + 0), n1y = __ldg(vnorm + 3 * i1 + 1), n1z = __ldg(vnorm + 3 * i1 + 2);
    float n2x = __ldg(vnorm + 3 * i2 + 0), n2y = __ldg(vnorm + 3 * i2 + 1), n2z = __ldg(vnorm + 3 * i2 + 2);

    float4* rec = g_face_table + (size_t)f * 8;
    rec[0] = make_float4(v0x, v0y, v0z, v1x);
    rec[1] = make_float4(v1y, v1z, v2x, v2y);
    rec[2] = make_float4(v2z, n0x, n0y, n0z);
    rec[3] = make_float4(n1x, n1y, n1z, n2x);
    rec[4] = make_float4(n2y, n2z, 0.0f, 0.0f);
}

// reference normalize: x / max(||x||, 1e-6)  ==  x * min(rsqrt(||x||^2), 1e6)
__device__ __forceinline__ float safe_rnorm(float n2)
{
    return fminf(rsqrtf(n2), 1e6f);
}

// 4-lane (k-group) butterfly reductions
__device__ __forceinline__ float red_sum4(float v)
{
    v += __shfl_xor_sync(0xffffffffu, v, 1);
    v += __shfl_xor_sync(0xffffffffu, v, 2);
    return v;
}
__device__ __forceinline__ float red_prod4(float v)
{
    v *= __shfl_xor_sync(0xffffffffu, v, 1);
    v *= __shfl_xor_sync(0xffffffffu, v, 2);
    return v;
}
__device__ __forceinline__ float red_max4(float v)
{
    v = fmaxf(v, __shfl_xor_sync(0xffffffffu, v, 1));
    v = fmaxf(v, __shfl_xor_sync(0xffffffffu, v, 2));
    return v;
}

// ---------------------------------------------------------------------------
// Kernel 2: shade + blend, ONE THREAD PER FRAGMENT (lane = 4*pixel + k).
//  - warp = 8 pixels * 4 fragments; single cooperative SMEM gather per warp
//  - all per-fragment streams flat-indexed -> perfectly coalesced
//  - K-blend via 4-lane butterfly reductions; k==0 lanes store the pixel
// ---------------------------------------------------------------------------
__global__ void __launch_bounds__(256)
shade(const float* __restrict__ bary,      // NFRAG*3 floats
      const float* __restrict__ zb,        // NFRAG
      const float* __restrict__ ds,        // NFRAG
      const float* __restrict__ tx,        // NFRAG*3
      const float* __restrict__ vis,       // NPIX*3
      const int*   __restrict__ p2f,       // NFRAG
      const float* __restrict__ l_loc,
      const float* __restrict__ l_amb,
      const float* __restrict__ l_dif,
      const float* __restrict__ l_spc,
      const float* __restrict__ cam,
      const float* __restrict__ m_amb,
      const float* __restrict__ m_dif,
      const float* __restrict__ m_spc,
      const float* __restrict__ shin,
      float4*      __restrict__ out)
{
    __shared__ float4 s_rec[8 * 160];      // 8 warps * 32 records * 5 float4 = 20KB
    const int Fg   = blockIdx.x * 256 + threadIdx.x;   // fragment id; grid covers NFRAG
    const int lane = threadIdx.x & 31;
    const int pix  = Fg >> 2;
    const int n    = Fg >> 20;             // = pix >> 18 (warp-uniform: 8 px per warp)

    // ---- fragment's face id (fully coalesced) gates the gather ----
    const int fk = __ldg(p2f + Fg);
    const int fc = max(fk, 0);

    // ---- cooperative record gather: 5 coalesced LDG.128 per warp ----
    float4* s = s_rec + (threadIdx.x >> 5) * 160;
#pragma unroll
    for (int j = 0; j < 5; j++) {
        const int t = j * 32 + lane;
        const int r = t / 5;
        const int p = t - 5 * r;
        const int fr = __shfl_sync(0xffffffffu, fc, r);
        s[t] = __ldg(reinterpret_cast<const float4*>(g_face_table) + (size_t)fr * 8 + p);
    }
    __syncwarp();
    const float4 a0 = s[lane * 5 + 0];     // stride-5 float4: conflict-free LDS.128
    const float4 a1 = s[lane * 5 + 1];
    const float4 a2 = s[lane * 5 + 2];
    const float4 a3 = s[lane * 5 + 3];
    const float4 a4 = s[lane * 5 + 4];

    // ---- per-image params (warp-uniform broadcast loads) ----
    const float llx = __ldg(l_loc + 3 * n), lly = __ldg(l_loc + 3 * n + 1), llz = __ldg(l_loc + 3 * n + 2);
    const float ccx = __ldg(cam   + 3 * n), ccy = __ldg(cam   + 3 * n + 1), ccz = __ldg(cam   + 3 * n + 2);
    const float ambr = __ldg(m_amb + 3 * n + 0) * __ldg(l_amb + 3 * n + 0);
    const float ambg = __ldg(m_amb + 3 * n + 1) * __ldg(l_amb + 3 * n + 1);
    const float ambb = __ldg(m_amb + 3 * n + 2) * __ldg(l_amb + 3 * n + 2);
    const float kdr  = __ldg(m_dif + 3 * n + 0) * __ldg(l_dif + 3 * n + 0);
    const float kdg  = __ldg(m_dif + 3 * n + 1) * __ldg(l_dif + 3 * n + 1);
    const float kdb  = __ldg(m_dif + 3 * n + 2) * __ldg(l_dif + 3 * n + 2);
    const float ksr  = __ldg(m_spc + 3 * n + 0) * __ldg(l_spc + 3 * n + 0);
    const float ksg  = __ldg(m_spc + 3 * n + 1) * __ldg(l_spc + 3 * n + 1);
    const float ksb  = __ldg(m_spc + 3 * n + 2) * __ldg(l_spc + 3 * n + 2);
    const float sh   = __ldg(shin + n);

    // ---- per-fragment streams (coalesced / near-coalesced) ----
    const float z  = __ldg(zb + Fg);
    const float d  = __ldg(ds + Fg);
    const float b0 = __ldg(bary + 3 * Fg + 0);
    const float b1 = __ldg(bary + 3 * Fg + 1);
    const float b2 = __ldg(bary + 3 * Fg + 2);
    const float tr = __ldg(tx + 3 * Fg + 0);
    const float tg = __ldg(tx + 3 * Fg + 1);
    const float tb = __ldg(tx + 3 * Fg + 2);
    const float vr = __ldg(vis + 3 * pix + 0);
    const float vg = __ldg(vis + 3 * pix + 1);
    const float vb = __ldg(vis + 3 * pix + 2);

    // ---- barycentric interpolation ----
    const float pcx = b0 * a0.x + b1 * a0.w + b2 * a1.z;
    const float pcy = b0 * a0.y + b1 * a1.x + b2 * a1.w;
    const float pcz = b0 * a0.z + b1 * a1.y + b2 * a2.x;
    const float pnx = b0 * a2.y + b1 * a3.x + b2 * a3.w;
    const float pny = b0 * a2.z + b1 * a3.y + b2 * a4.x;
    const float pnz = b0 * a2.w + b1 * a3.z + b2 * a4.y;

    // ---- Phong shading ----
    const float rn = safe_rnorm(pnx * pnx + pny * pny + pnz * pnz);
    const float nx = pnx * rn, ny = pny * rn, nz = pnz * rn;

    float dx = llx - pcx, dy = lly - pcy, dz = llz - pcz;
    const float rd = safe_rnorm(dx * dx + dy * dy + dz * dz);
    dx *= rd; dy *= rd; dz *= rd;

    const float cosA = nx * dx + ny * dy + nz * dz;
    const float rc   = fmaxf(cosA, 0.0f);

    const float rfx = 2.0f * cosA * nx - dx;
    const float rfy = 2.0f * cosA * ny - dy;
    const float rfz = 2.0f * cosA * nz - dz;

    const float vx = ccx - pcx, vy = ccy - pcy, vz = ccz - pcz;
    const float rv = safe_rnorm(vx * vx + vy * vy + vz * vz);
    float sc = (vx * rfx + vy * rfy + vz * rfz) * rv;
    sc = fmaxf(sc, 0.0f);
    const float spec = (cosA > 0.0f && sc > 0.0f) ? __powf(sc, sh) : 0.0f;

    const float cr = (ambr + kdr * rc * vr) * tr + ksr * spec;
    const float cg = (ambg + kdg * rc * vg) * tg + ksg * spec;
    const float cb = (ambb + kdb * rc * vb) * tb + ksb * spec;

    // ---- blend inputs (masked fragments carry weight 0) ----
    const bool  m    = (fk >= 0);
    const float prob = m ? __fdividef(1.0f, 1.0f + __expf(d * SIGMA_INV)) : 0.0f;
    const float zi   = m ? (ZFARC - z) * INV_ZRANGE : 0.0f;

    // ---- K-reduction across the 4-lane group ----
    const float zmax = fmaxf(red_max4(zi), EPSB);
    const float w    = prob * __expf((zi - zmax) * GAMMA_INV);

    const float wsum = red_sum4(w);
    const float sr   = red_sum4(w * cr);
    const float sg   = red_sum4(w * cg);
    const float sb   = red_sum4(w * cb);
    const float pm   = red_prod4(1.0f - prob);

    if ((lane & 3) == 0) {
        const float delta = __expf((EPSB - zmax) * GAMMA_INV);
        const float inv   = 1.0f / (wsum + delta);   // BG=(1,1,1) -> delta*BG = delta
        out[pix] = make_float4((sr + delta) * inv, (sg + delta) * inv,
                               (sb + delta) * inv, 1.0f - pm);
    }
}

// ---------------------------------------------------------------------------
// Input order (metadata.txt / setup_inputs order):
//  0 verts  1 vertex_normals  2 bary_coords  3 zbuf  4 dists  5 texels
//  6 vis_maps  7 light_location  8 light_ambient  9 light_diffuse
// 10 light_specular 11 camera_center 12 mat_ambient 13 mat_diffuse
// 14 mat_specular 15 shininess 16 faces 17 pix_to_face
// ---------------------------------------------------------------------------
extern "C" void kernel_launch(void* const* d_in, const int* in_sizes, int n_in,
                              void* d_out, int out_size)
{
    (void)in_sizes; (void)n_in; (void)out_size;

    const float* verts  = (const float*)d_in[0];
    const float* vnorm  = (const float*)d_in[1];
    const float* bary   = (const float*)d_in[2];
    const float* zbuf   = (const float*)d_in[3];
    const float* dists  = (const float*)d_in[4];
    const float* texels = (const float*)d_in[5];
    const float* vis    = (const float*)d_in[6];
    const float* l_loc  = (const float*)d_in[7];
    const float* l_amb  = (const float*)d_in[8];
    const float* l_dif  = (const float*)d_in[9];
    const float* l_spc  = (const float*)d_in[10];
    const float* cam    = (const float*)d_in[11];
    const float* m_amb  = (const float*)d_in[12];
    const float* m_dif  = (const float*)d_in[13];
    const float* m_spc  = (const float*)d_in[14];
    const float* shin   = (const float*)d_in[15];
    const int*   faces  = (const int*)d_in[16];
    const int*   p2f    = (const int*)d_in[17];
    float4* out = (float4*)d_out;

    pack_faces<<<(FCOUNT + 255) / 256, 256>>>(faces, verts, vnorm);
    shade<<<NFRAG / 256, 256>>>(bary, zbuf, dists, texels, vis, p2f,
                                l_loc, l_amb, l_dif, l_spc, cam,
                                m_amb, m_dif, m_spc, shin, out);
}

// round 17
// speedup vs baseline: 7.9052x; 1.0283x over previous
#include <cuda_runtime.h>
#include <cstdint>

// Problem constants (fixed shapes from the reference)
#define NPIX    (8 * 512 * 512)     // N*H*W = 2,097,152
#define NFRAG   (NPIX * 4)          // 8,388,608 fragments (K=4)
#define NIMG    8
#define FCOUNT  100000
#define SIGMA_INV   10000.0f        // 1/SIGMA
#define GAMMA_INV   10000.0f        // 1/GAMMA
#define ZFARC       100.0f
#define INV_ZRANGE  (1.0f / 99.0f)  // 1/(ZFAR-ZNEAR)
#define EPSB        1e-10f

// Packed per-face records: 128B-aligned, 5 float4s used (18 floats):
//  [v0.xyz v1.x | v1.yz v2.xy | v2.z n0.xyz | n1.xyz n2.x | n2.yz - -]
__device__ float4 g_face_table[(size_t)FCOUNT * 8];   // 12.8 MB static scratch

// Packed per-image params, 4 float4 per image:
//  P0 = (llx,lly,llz, ccx)  P1 = (ccy,ccz, ambr,ambg)
//  P2 = (ambb, kdr,kdg,kdb) P3 = (ksr,ksg,ksb, sh)
__device__ float4 g_params[NIMG * 4];

// ---------------------------------------------------------------------------
// Kernel 1: gather verts/normals per face into line-aligned records,
// and (threads 0..7) precompute the packed per-image param blocks.
// ---------------------------------------------------------------------------
__global__ void __launch_bounds__(256)
pack_faces(const int* __restrict__ faces,
           const float* __restrict__ verts,
           const float* __restrict__ vnorm,
           const float* __restrict__ l_loc,
           const float* __restrict__ l_amb,
           const float* __restrict__ l_dif,
           const float* __restrict__ l_spc,
           const float* __restrict__ cam,
           const float* __restrict__ m_amb,
           const float* __restrict__ m_dif,
           const float* __restrict__ m_spc,
           const float* __restrict__ shin)
{
    int f = blockIdx.x * blockDim.x + threadIdx.x;
    if (f >= FCOUNT) return;

    if (f < NIMG) {
        const int n = f;
        g_params[4 * n + 0] = make_float4(l_loc[3 * n], l_loc[3 * n + 1], l_loc[3 * n + 2],
                                          cam[3 * n]);
        g_params[4 * n + 1] = make_float4(cam[3 * n + 1], cam[3 * n + 2],
                                          m_amb[3 * n + 0] * l_amb[3 * n + 0],
                                          m_amb[3 * n + 1] * l_amb[3 * n + 1]);
        g_params[4 * n + 2] = make_float4(m_amb[3 * n + 2] * l_amb[3 * n + 2],
                                          m_dif[3 * n + 0] * l_dif[3 * n + 0],
                                          m_dif[3 * n + 1] * l_dif[3 * n + 1],
                                          m_dif[3 * n + 2] * l_dif[3 * n + 2]);
        g_params[4 * n + 3] = make_float4(m_spc[3 * n + 0] * l_spc[3 * n + 0],
                                          m_spc[3 * n + 1] * l_spc[3 * n + 1],
                                          m_spc[3 * n + 2] * l_spc[3 * n + 2],
                                          shin[n]);
    }

    int i0 = __ldg(faces + 3 * f + 0);
    int i1 = __ldg(faces + 3 * f + 1);
    int i2 = __ldg(faces + 3 * f + 2);

    float v0x = __ldg(verts + 3 * i0 + 0), v0y = __ldg(verts + 3 * i0 + 1), v0z = __ldg(verts + 3 * i0 + 2);
    float v1x = __ldg(verts + 3 * i1 + 0), v1y = __ldg(verts + 3 * i1 + 1), v1z = __ldg(verts + 3 * i1 + 2);
    float v2x = __ldg(verts + 3 * i2 + 0), v2y = __ldg(verts + 3 * i2 + 1), v2z = __ldg(verts + 3 * i2 + 2);
    float n0x = __ldg(vnorm + 3 * i0 + 0), n0y = __ldg(vnorm + 3 * i0 + 1), n0z = __ldg(vnorm + 3 * i0 + 2);
    float n1x = __ldg(vnorm + 3 * i1 + 0), n1y = __ldg(vnorm + 3 * i1 + 1), n1z = __ldg(vnorm + 3 * i1 + 2);
    float n2x = __ldg(vnorm + 3 * i2 + 0), n2y = __ldg(vnorm + 3 * i2 + 1), n2z = __ldg(vnorm + 3 * i2 + 2);

    float4* rec = g_face_table + (size_t)f * 8;
    rec[0] = make_float4(v0x, v0y, v0z, v1x);
    rec[1] = make_float4(v1y, v1z, v2x, v2y);
    rec[2] = make_float4(v2z, n0x, n0y, n0z);
    rec[3] = make_float4(n1x, n1y, n1z, n2x);
    rec[4] = make_float4(n2y, n2z, 0.0f, 0.0f);
}

// reference normalize: x / max(||x||, 1e-6)  ==  x * min(rsqrt(||x||^2), 1e6)
__device__ __forceinline__ float safe_rnorm(float n2)
{
    return fminf(rsqrtf(n2), 1e6f);
}

// 4-lane (k-group) butterfly reductions
__device__ __forceinline__ float red_sum4(float v)
{
    v += __shfl_xor_sync(0xffffffffu, v, 1);
    v += __shfl_xor_sync(0xffffffffu, v, 2);
    return v;
}
__device__ __forceinline__ float red_prod4(float v)
{
    v *= __shfl_xor_sync(0xffffffffu, v, 1);
    v *= __shfl_xor_sync(0xffffffffu, v, 2);
    return v;
}
__device__ __forceinline__ float red_max4(float v)
{
    v = fmaxf(v, __shfl_xor_sync(0xffffffffu, v, 1));
    v = fmaxf(v, __shfl_xor_sync(0xffffffffu, v, 2));
    return v;
}

// ---------------------------------------------------------------------------
// Kernel 2: shade + blend, one thread per fragment (lane = 4*pixel + k).
//  - warp = 8 pixels * 4 fragments; single cooperative SMEM gather per warp
//  - per-image params: 4 x LDG.128 from the packed block (was 19 scalar LDGs)
//  - b2 = 1 - b0 - b1 (saves one stride-3 stream load)
// ---------------------------------------------------------------------------
__global__ void __launch_bounds__(256)
shade(const float* __restrict__ bary,      // NFRAG*3 floats
      const float* __restrict__ zb,        // NFRAG
      const float* __restrict__ ds,        // NFRAG
      const float* __restrict__ tx,        // NFRAG*3
      const float* __restrict__ vis,       // NPIX*3
      const int*   __restrict__ p2f,       // NFRAG
      float4*      __restrict__ out)
{
    __shared__ float4 s_rec[8 * 160];      // 8 warps * 32 records * 5 float4 = 20KB
    const int Fg   = blockIdx.x * 256 + threadIdx.x;   // fragment id; grid covers NFRAG
    const int lane = threadIdx.x & 31;
    const int pix  = Fg >> 2;
    const int n    = Fg >> 20;             // fragments per image = 2^20 (warp-uniform)

    // ---- fragment's face id (fully coalesced) gates the gather ----
    const int fk = __ldg(p2f + Fg);
    const int fc = max(fk, 0);

    // ---- cooperative record gather: 5 coalesced LDG.128 per warp ----
    float4* s = s_rec + (threadIdx.x >> 5) * 160;
#pragma unroll
    for (int j = 0; j < 5; j++) {
        const int t = j * 32 + lane;
        const int r = t / 5;
        const int p = t - 5 * r;
        const int fr = __shfl_sync(0xffffffffu, fc, r);
        s[t] = __ldg(reinterpret_cast<const float4*>(g_face_table) + (size_t)fr * 8 + p);
    }
    __syncwarp();
    const float4 a0 = s[lane * 5 + 0];     // stride-5 float4: conflict-free LDS.128
    const float4 a1 = s[lane * 5 + 1];
    const float4 a2 = s[lane * 5 + 2];
    const float4 a3 = s[lane * 5 + 3];
    const float4 a4 = s[lane * 5 + 4];

    // ---- per-image params: 4 vector loads (L1-resident, warp-uniform) ----
    const float4 P0 = __ldg(g_params + 4 * n + 0);
    const float4 P1 = __ldg(g_params + 4 * n + 1);
    const float4 P2 = __ldg(g_params + 4 * n + 2);
    const float4 P3 = __ldg(g_params + 4 * n + 3);
    const float llx = P0.x, lly = P0.y, llz = P0.z;
    const float ccx = P0.w, ccy = P1.x, ccz = P1.y;
    const float ambr = P1.z, ambg = P1.w, ambb = P2.x;
    const float kdr = P2.y, kdg = P2.z, kdb = P2.w;
    const float ksr = P3.x, ksg = P3.y, ksb = P3.z;
    const float sh  = P3.w;

    // ---- per-fragment streams (coalesced / near-coalesced) ----
    const float z  = __ldg(zb + Fg);
    const float d  = __ldg(ds + Fg);
    const float b0 = __ldg(bary + 3 * Fg + 0);
    const float b1 = __ldg(bary + 3 * Fg + 1);
    const float b2 = 1.0f - b0 - b1;       // rows sum to 1 (±1 ulp)
    const float tr = __ldg(tx + 3 * Fg + 0);
    const float tg = __ldg(tx + 3 * Fg + 1);
    const float tb = __ldg(tx + 3 * Fg + 2);
    const float vr = __ldg(vis + 3 * pix + 0);
    const float vg = __ldg(vis + 3 * pix + 1);
    const float vb = __ldg(vis + 3 * pix + 2);

    // ---- barycentric interpolation ----
    const float pcx = b0 * a0.x + b1 * a0.w + b2 * a1.z;
    const float pcy = b0 * a0.y + b1 * a1.x + b2 * a1.w;
    const float pcz = b0 * a0.z + b1 * a1.y + b2 * a2.x;
    const float pnx = b0 * a2.y + b1 * a3.x + b2 * a3.w;
    const float pny = b0 * a2.z + b1 * a3.y + b2 * a4.x;
    const float pnz = b0 * a2.w + b1 * a3.z + b2 * a4.y;

    // ---- Phong shading ----
    const float rn = safe_rnorm(pnx * pnx + pny * pny + pnz * pnz);
    const float nx = pnx * rn, ny = pny * rn, nz = pnz * rn;

    float dx = llx - pcx, dy = lly - pcy, dz = llz - pcz;
    const float rd = safe_rnorm(dx * dx + dy * dy + dz * dz);
    dx *= rd; dy *= rd; dz *= rd;

    const float cosA = nx * dx + ny * dy + nz * dz;
    const float rc   = fmaxf(cosA, 0.0f);

    const float rfx = 2.0f * cosA * nx - dx;
    const float rfy = 2.0f * cosA * ny - dy;
    const float rfz = 2.0f * cosA * nz - dz;

    const float vx = ccx - pcx, vy = ccy - pcy, vz = ccz - pcz;
    const float rv = safe_rnorm(vx * vx + vy * vy + vz * vz);
    float sc = (vx * rfx + vy * rfy + vz * rfz) * rv;
    sc = fmaxf(sc, 0.0f);
    const float spec = (cosA > 0.0f && sc > 0.0f) ? __powf(sc, sh) : 0.0f;

    const float cr = (ambr + kdr * rc * vr) * tr + ksr * spec;
    const float cg = (ambg + kdg * rc * vg) * tg + ksg * spec;
    const float cb = (ambb + kdb * rc * vb) * tb + ksb * spec;

    // ---- blend inputs (masked fragments carry weight 0) ----
    const bool  m    = (fk >= 0);
    const float prob = m ? __fdividef(1.0f, 1.0f + __expf(d * SIGMA_INV)) : 0.0f;
    const float zi   = m ? (ZFARC - z) * INV_ZRANGE : 0.0f;

    // ---- K-reduction across the 4-lane group ----
    const float zmax = fmaxf(red_max4(zi), EPSB);
    const float w    = prob * __expf((zi - zmax) * GAMMA_INV);

    const float wsum = red_sum4(w);
    const float sr   = red_sum4(w * cr);
    const float sg   = red_sum4(w * cg);
    const float sb   = red_sum4(w * cb);
    const float pm   = red_prod4(1.0f - prob);

    if ((lane & 3) == 0) {
        const float delta = __expf((EPSB - zmax) * GAMMA_INV);
        const float inv   = 1.0f / (wsum + delta);   // BG=(1,1,1) -> delta*BG = delta
        out[pix] = make_float4((sr + delta) * inv, (sg + delta) * inv,
                               (sb + delta) * inv, 1.0f - pm);
    }
}

// ---------------------------------------------------------------------------
// Input order (metadata.txt / setup_inputs order):
//  0 verts  1 vertex_normals  2 bary_coords  3 zbuf  4 dists  5 texels
//  6 vis_maps  7 light_location  8 light_ambient  9 light_diffuse
// 10 light_specular 11 camera_center 12 mat_ambient 13 mat_diffuse
// 14 mat_specular 15 shininess 16 faces 17 pix_to_face
// ---------------------------------------------------------------------------
extern "C" void kernel_launch(void* const* d_in, const int* in_sizes, int n_in,
                              void* d_out, int out_size)
{
    (void)in_sizes; (void)n_in; (void)out_size;

    const float* verts  = (const float*)d_in[0];
    const float* vnorm  = (const float*)d_in[1];
    const float* bary   = (const float*)d_in[2];
    const float* zbuf   = (const float*)d_in[3];
    const float* dists  = (const float*)d_in[4];
    const float* texels = (const float*)d_in[5];
    const float* vis    = (const float*)d_in[6];
    const float* l_loc  = (const float*)d_in[7];
    const float* l_amb  = (const float*)d_in[8];
    const float* l_dif  = (const float*)d_in[9];
    const float* l_spc  = (const float*)d_in[10];
    const float* cam    = (const float*)d_in[11];
    const float* m_amb  = (const float*)d_in[12];
    const float* m_dif  = (const float*)d_in[13];
    const float* m_spc  = (const float*)d_in[14];
    const float* shin   = (const float*)d_in[15];
    const int*   faces  = (const int*)d_in[16];
    const int*   p2f    = (const int*)d_in[17];
    float4* out = (float4*)d_out;

    pack_faces<<<(FCOUNT + 255) / 256, 256>>>(faces, verts, vnorm,
                                              l_loc, l_amb, l_dif, l_spc, cam,
                                              m_amb, m_dif, m_spc, shin);
    shade<<<NFRAG / 256, 256>>>(bary, zbuf, dists, texels, vis, p2f, out);
}